// round 8
// baseline (speedup 1.0000x reference)
#include <cuda_runtime.h>

// MinConv2d: 3x3 min-pool, stride 1, pad 1 (zero padding PARTICIPATES in min).
// Input/output: (8, 64, 512, 512) fp32 -> 512 planes of 512x512.
//
// R5 = R4 resubmitted (previous run was a container infra failure):
//  - separable rolling min, loads batched 4 rows for MLP
//  - ROWS_PER_BLOCK 64 (less overlap re-read, longer-lived blocks)
//  - warp shuffle for horizontal neighbors (lanes 0/31 edge-load only)
//  - streaming stores (__stcs): output is never re-read.

#define PLANE_H 512
#define PLANE_W 512
#define ROWS_PER_BLOCK 64
#define THREADS 128   // 128 * 4 floats = 512 = full row width

__device__ __forceinline__ float4 fmin4(float4 a, float4 b) {
    return make_float4(fminf(a.x, b.x), fminf(a.y, b.y),
                       fminf(a.z, b.z), fminf(a.w, b.w));
}

__global__ __launch_bounds__(THREADS)
void minpool3x3_kernel(const float* __restrict__ x, float* __restrict__ out) {
    const int plane = blockIdx.y;
    const float* __restrict__ xp = x + (size_t)plane * PLANE_H * PLANE_W;
    float* __restrict__ op = out + (size_t)plane * PLANE_H * PLANE_W;

    const int base = threadIdx.x * 4;
    const int lane = threadIdx.x & 31;
    const int y0   = blockIdx.x * ROWS_PER_BLOCK;
    // Edge loads only for the boundary lanes of each warp (cross-warp strip
    // neighbors aren't shuffle-reachable). At the image border the neighbor
    // is the zero pad (edge flag false -> 0.0f).
    const bool edgeL = (lane == 0)  && (base != 0);
    const bool edgeR = (lane == 31) && (base + 4 != PLANE_W);

    // Horizontal 3-min with shuffle neighbors; zeroed for padded rows.
    auto hmin = [&](float4 v, float eL, float eR, bool valid) -> float4 {
        float l = __shfl_up_sync(0xffffffffu, v.w, 1);
        float r = __shfl_down_sync(0xffffffffu, v.x, 1);
        if (lane == 0)  l = eL;
        if (lane == 31) r = eR;
        float4 h;
        h.x = fminf(l,   fminf(v.x, v.y));
        h.y = fminf(v.x, fminf(v.y, v.z));
        h.z = fminf(v.y, fminf(v.z, v.w));
        h.w = fminf(v.z, fminf(v.w, r));
        if (!valid) h = make_float4(0.f, 0.f, 0.f, 0.f);
        return h;
    };

    // ---- prologue: input rows y0-1 and y0 ----
    float4 h2, h1;
    {
        const int yi = y0 - 1;
        const int yc = yi < 0 ? 0 : yi;
        const float* row = xp + (size_t)yc * PLANE_W + base;
        float4 v = *reinterpret_cast<const float4*>(row);
        float eL = edgeL ? __ldg(row - 1) : 0.0f;
        float eR = edgeR ? __ldg(row + 4) : 0.0f;
        h2 = hmin(v, eL, eR, yi >= 0);
    }
    {
        const float* row = xp + (size_t)y0 * PLANE_W + base;
        float4 v = *reinterpret_cast<const float4*>(row);
        float eL = edgeL ? __ldg(row - 1) : 0.0f;
        float eR = edgeR ? __ldg(row + 4) : 0.0f;
        h1 = hmin(v, eL, eR, true);
    }

    // ---- steady state: rows y0+1 .. y0+64, batched 4 at a time ----
    for (int r0 = 1; r0 <= ROWS_PER_BLOCK; r0 += 4) {
        float4 v[4];
        float  eL[4], eR[4];
        bool   val[4];

        #pragma unroll
        for (int j = 0; j < 4; ++j) {
            const int yi = y0 + r0 + j;                       // may be 512 (pad)
            const int yc = yi < PLANE_H ? yi : PLANE_H - 1;   // clamp: load legal
            const float* row = xp + (size_t)yc * PLANE_W + base;
            v[j]   = *reinterpret_cast<const float4*>(row);
            eL[j]  = edgeL ? __ldg(row - 1) : 0.0f;
            eR[j]  = edgeR ? __ldg(row + 4) : 0.0f;
            val[j] = yi < PLANE_H;
        }

        #pragma unroll
        for (int j = 0; j < 4; ++j) {
            const float4 h = hmin(v[j], eL[j], eR[j], val[j]);
            const int yo = y0 + r0 + j - 1;
            float4 o = fmin4(h2, fmin4(h1, h));
            __stcs(reinterpret_cast<float4*>(op + (size_t)yo * PLANE_W + base), o);
            h2 = h1;
            h1 = h;
        }
    }
}

extern "C" void kernel_launch(void* const* d_in, const int* in_sizes, int n_in,
                              void* d_out, int out_size) {
    const float* x = (const float*)d_in[0];
    float* out = (float*)d_out;

    const int planes = 8 * 64;                       // 512
    dim3 grid(PLANE_H / ROWS_PER_BLOCK, planes);     // (8, 512) = 4096 blocks
    dim3 block(THREADS);
    minpool3x3_kernel<<<grid, block>>>(x, out);
}